// round 12
// baseline (speedup 1.0000x reference)
#include <cuda_runtime.h>

//
// Morphological skeleton — merged erode+dilate, one smem pass per iteration.
// R11 = R10 scaled up: 22 strips x 7 rows => 836 threads (27 warps) instead
// of 19x8=722. Latency-bound kernel (no saturated pipe) -> keep adding warps;
// RPS=7 trims acc registers so 836 threads fit the 64K-reg file.
//
//   skel = sum_{j=0..K-1} x_j  -  sum_{j=1..K} dilate3(x_j),  x_{j+1} = erode3(x_j)
//

#define IMG    1024
#define NIMG   16
#define TILE   128
#define HALO   12
#define RW     152                 /* region valid width/height   */
#define RWP    164                 /* padded row stride: 164%32=4 avoids cross-strip bank aliasing */
#define NCOL   38                  /* float4 columns: exactly covers 152 */
#define NSTR   22
#define NT     (NCOL*NSTR)         /* 836 threads = 27 warps      */
#define RPS    7                   /* rows per strip: 22*7 = 154 >= 152 */
#define SMEMB  (2 * RW * RWP * 4)  /* 199424 bytes                */

__device__ float g_scratch[(size_t)NIMG * IMG * IMG];

__device__ __forceinline__ float min3f(float a, float b, float c) { return fminf(fminf(a, b), c); }
__device__ __forceinline__ float max3f(float a, float b, float c) { return fmaxf(fmaxf(a, b), c); }

// One row-block: 1x LDS.128 + 2x independent scalar LDS (no shuffles — the
// scalar loads overlap with the vector load; shfl serializes, measured 2x).
__device__ __forceinline__ void rowmm(const float* __restrict__ row, int xb,
                                      float4& v, float4& mn, float4& mx,
                                      bool doMn, bool doMx)
{
    v = *(const float4*)(row + xb);
    float l = (xb > 0)       ? row[xb - 1] : v.x;   // region-edge replicate (min-safe;
    float r = (xb + 4 < RW)  ? row[xb + 4] : v.w;   //  never feeds interior dilate)
    if (doMn) {
        mn.x = min3f(l,   v.x, v.y);
        mn.y = min3f(v.x, v.y, v.z);
        mn.z = min3f(v.y, v.z, v.w);
        mn.w = min3f(v.z, v.w, r);
    }
    if (doMx) {
        mx.x = max3f(l,   v.x, v.y);
        mx.y = max3f(v.x, v.y, v.z);
        mx.z = max3f(v.y, v.z, v.w);
        mx.w = max3f(v.z, v.w, r);
    }
}

__global__ void __launch_bounds__(NT, 1)
skel_merged_kernel(const float* __restrict__ xin,
                   float* __restrict__ xout,
                   float* __restrict__ skel,
                   int K, int accum, int writex)
{
    extern __shared__ float smem[];
    float* cur = smem;             // x_p
    float* nxt = smem + RW * RWP;  // receives x_{p+1}

    const int tid = threadIdx.x;
    const int bx = blockIdx.x, by = blockIdx.y, bz = blockIdx.z;
    const int gx0 = bx * TILE - HALO;
    const int gy0 = by * TILE - HALO;
    const float* img = xin + (size_t)bz * IMG * IMG;

    // ---- load region with replicate clamp ----
    for (int i = tid; i < RW * RW; i += NT) {
        int y = i / RW;
        int x = i - y * RW;
        int gy = min(max(gy0 + y, 0), IMG - 1);
        int gx = min(max(gx0 + x, 0), IMG - 1);
        cur[y * RWP + x] = img[(size_t)gy * IMG + gx];
    }
    __syncthreads();

    const bool topE   = (by == 0);
    const bool botE   = (by == (int)gridDim.y - 1);
    const bool leftE  = (bx == 0);
    const bool rightE = (bx == (int)gridDim.x - 1);
    const bool anyE   = topE || botE || leftE || rightE;

    const int c  = tid % NCOL;                   // float4 column 0..37
    const int s  = tid / NCOL;                   // strip 0..21
    const int xb = c * 4;                        // 0..148
    const bool dcol = (xb >= HALO) && (xb + 4 <= HALO + TILE);  // interior col block
    const int y0 = s * RPS;

    float4 acc[RPS];
#pragma unroll
    for (int k = 0; k < RPS; k++) acc[k] = make_float4(0.f, 0.f, 0.f, 0.f);

    for (int p = 0; p <= K; ++p) {
        const bool doE = (p < K);
        const bool doD = (p > 0);
        const bool doMx = doD && dcol;           // hmax consumed only here
        const int  m   = K - p;                  // erode validity margin
        const int  elo = doE ? (HALO - m) : HALO;
        const int  ehi = doE ? (HALO + TILE + m) : (HALO + TILE);

        if (doE || dcol) {
            // prime 3-row ring (vertical replicate clamp; min-safe, clamped
            // rows never reach interior dilate consumers)
            float4 av, amn, amx, bv, bmn, bmx;
            rowmm(cur + min(max(y0 - 1, 0), RW - 1) * RWP, xb, av, amn, amx, doE, doMx);
            rowmm(cur + min(y0, RW - 1) * RWP,             xb, bv, bmn, bmx, doE, doMx);

#pragma unroll
            for (int k = 0; k < RPS; k++) {
                const int y = y0 + k;
                float4 cv, cmn, cmx;
                rowmm(cur + min(y + 1, RW - 1) * RWP, xb, cv, cmn, cmx, doE, doMx);

                // skel terms at interior rows: += x_p (p<K), -= dilate(x_p) (p>0)
                if (dcol && y >= HALO && y < HALO + TILE) {
                    if (doMx) {
                        acc[k].x -= max3f(amx.x, bmx.x, cmx.x);
                        acc[k].y -= max3f(amx.y, bmx.y, cmx.y);
                        acc[k].z -= max3f(amx.z, bmx.z, cmx.z);
                        acc[k].w -= max3f(amx.w, bmx.w, cmx.w);
                    }
                    if (doE) {
                        acc[k].x += bv.x; acc[k].y += bv.y;
                        acc[k].z += bv.z; acc[k].w += bv.w;
                    }
                }
                // erode -> x_{p+1}
                if (doE && y >= elo && y < ehi) {
                    float4 e;
                    e.x = min3f(amn.x, bmn.x, cmn.x);
                    e.y = min3f(amn.y, bmn.y, cmn.y);
                    e.z = min3f(amn.z, bmn.z, cmn.z);
                    e.w = min3f(amn.w, bmn.w, cmn.w);
                    *(float4*)(nxt + y * RWP + xb) = e;
                }
                av = bv; amn = bmn; amx = bmx;
                bv = cv; bmn = cmn; bmx = cmx;
            }
        }
        __syncthreads();

        // image-border ring fix-up on freshly eroded buffer (edge blocks only)
        if (doE && anyE) {
            if (tid < TILE + 2) {
                int o = HALO - 1 + tid;                    // 11..140
                int sx = o;
                if (leftE  && sx < HALO)             sx = HALO;
                if (rightE && sx > HALO + TILE - 1)  sx = HALO + TILE - 1;
                int sy = o;
                if (topE && sy < HALO)               sy = HALO;
                if (botE && sy > HALO + TILE - 1)    sy = HALO + TILE - 1;
                if (topE)   nxt[(HALO - 1) * RWP + o]      = nxt[HALO * RWP + sx];
                if (botE)   nxt[(HALO + TILE) * RWP + o]   = nxt[(HALO + TILE - 1) * RWP + sx];
                if (leftE)  nxt[o * RWP + (HALO - 1)]      = nxt[sy * RWP + HALO];
                if (rightE) nxt[o * RWP + (HALO + TILE)]   = nxt[sy * RWP + (HALO + TILE - 1)];
            }
            __syncthreads();
        }

        if (doE) { float* t = cur; cur = nxt; nxt = t; }
    }

    // ---- outputs ----
    if (dcol) {
        float* so = skel + (size_t)bz * IMG * IMG;
        float* xo = xout + (size_t)bz * IMG * IMG;
#pragma unroll
        for (int k = 0; k < RPS; k++) {
            const int y = y0 + k;
            if (y >= HALO && y < HALO + TILE) {
                const size_t off = (size_t)(by * TILE + (y - HALO)) * IMG
                                 + (size_t)(bx * TILE + (xb - HALO));
                if (writex)
                    *(float4*)(xo + off) = *(const float4*)(cur + y * RWP + xb);
                if (accum) {
                    float4 sv = *(const float4*)(so + off);
                    sv.x += acc[k].x; sv.y += acc[k].y;
                    sv.z += acc[k].z; sv.w += acc[k].w;
                    *(float4*)(so + off) = sv;
                } else {
                    *(float4*)(so + off) = acc[k];
                }
            }
        }
    }
}

extern "C" void kernel_launch(void* const* d_in, const int* in_sizes, int n_in,
                              void* d_out, int out_size)
{
    (void)in_sizes; (void)n_in; (void)out_size;
    const float* x = (const float*)d_in[0];
    float* skel = (float*)d_out;

    float* scratch = nullptr;
    cudaGetSymbolAddress((void**)&scratch, g_scratch);

    cudaFuncSetAttribute(skel_merged_kernel,
                         cudaFuncAttributeMaxDynamicSharedMemorySize, SMEMB);

    dim3 grid(IMG / TILE, IMG / TILE, NIMG);   // 8 x 8 x 16
    // iterations 0..10 (11 terms): init skel, write x_11 to scratch
    skel_merged_kernel<<<grid, NT, SMEMB>>>(x, scratch, skel, 11, 0, 1);
    // iterations 11..20 (10 terms): accumulate skel
    skel_merged_kernel<<<grid, NT, SMEMB>>>(scratch, scratch, skel, 10, 1, 0);
}

// round 13
// speedup vs baseline: 1.0275x; 1.0275x over previous
#include <cuda_runtime.h>

//
// Morphological skeleton — merged erode+dilate, one smem pass per iteration.
// R12 = R10 (best: 492us; 19 strips x 8 rows, 722 thr, AoS float4 + scalar
// neighbor LDS) with:
//   - register clipping of dilate operands at image borders (fix-up pass and
//     its second barrier deleted; replicate-init keeps erosion exact)
//   - idle-strip gating per pass (strips outside the erode-store band and
//     dilate band skip straight to the barrier)
//   - vectorized initial region load for x-interior CTAs
//
//   skel = sum_{j=0..K-1} x_j  -  sum_{j=1..K} dilate3(x_j),  x_{j+1} = erode3(x_j)
//

#define IMG    1024
#define NIMG   16
#define TILE   128
#define HALO   12
#define RW     152                 /* region valid width/height   */
#define RWP    164                 /* padded row stride: 164%32=4 avoids cross-strip bank aliasing */
#define NCOL   38                  /* float4 columns: exactly covers 152 */
#define NSTR   19
#define NT     (NCOL*NSTR)         /* 722 threads ~ 22.6 warps    */
#define RPS    8                   /* rows per strip: 19*8 = 152 exactly */
#define SMEMB  (2 * RW * RWP * 4)  /* 199424 bytes                */

__device__ float g_scratch[(size_t)NIMG * IMG * IMG];

__device__ __forceinline__ float min3f(float a, float b, float c) { return fminf(fminf(a, b), c); }
__device__ __forceinline__ float max3f(float a, float b, float c) { return fmaxf(fmaxf(a, b), c); }

// One row-block: 1x LDS.128 + 2x independent scalar LDS (no shuffles — the
// scalar loads overlap with the vector load; shfl serializes, measured 2x).
// For the hmax path, l/r are replaced by the center at image-edge columns
// (clipped max in registers).
__device__ __forceinline__ void rowmm(const float* __restrict__ row, int xb,
                                      float4& v, float4& mn, float4& mx,
                                      bool doMn, bool doMx, bool lClip, bool rClip)
{
    v = *(const float4*)(row + xb);
    float l = (xb > 0)       ? row[xb - 1] : v.x;   // region-edge replicate (min-safe)
    float r = (xb + 4 < RW)  ? row[xb + 4] : v.w;
    if (doMn) {
        mn.x = min3f(l,   v.x, v.y);
        mn.y = min3f(v.x, v.y, v.z);
        mn.z = min3f(v.y, v.z, v.w);
        mn.w = min3f(v.z, v.w, r);
    }
    if (doMx) {
        const float lx = lClip ? v.x : l;           // clipped dilate at image edge
        const float rx = rClip ? v.w : r;
        mx.x = max3f(lx,  v.x, v.y);
        mx.y = max3f(v.x, v.y, v.z);
        mx.z = max3f(v.y, v.z, v.w);
        mx.w = max3f(v.z, v.w, rx);
    }
}

__global__ void __launch_bounds__(NT, 1)
skel_merged_kernel(const float* __restrict__ xin,
                   float* __restrict__ xout,
                   float* __restrict__ skel,
                   int K, int accum, int writex)
{
    extern __shared__ float smem[];
    float* cur = smem;             // x_p
    float* nxt = smem + RW * RWP;  // receives x_{p+1}

    const int tid = threadIdx.x;
    const int bx = blockIdx.x, by = blockIdx.y, bz = blockIdx.z;
    const int gx0 = bx * TILE - HALO;
    const int gy0 = by * TILE - HALO;
    const float* img = xin + (size_t)bz * IMG * IMG;

    // ---- load region (vector fast path when x-interior) ----
    if (gx0 >= 0 && gx0 + RW <= IMG) {
        for (int u = tid; u < RW * NCOL; u += NT) {
            const int y = u / NCOL, c = u - y * NCOL;
            const int gy = min(max(gy0 + y, 0), IMG - 1);
            const float4 v = *(const float4*)(img + (size_t)gy * IMG + gx0 + 4 * c);
            *(float4*)(cur + y * RWP + 4 * c) = v;
        }
    } else {
        for (int i = tid; i < RW * RW; i += NT) {
            const int y = i / RW;
            const int x = i - y * RW;
            const int gy = min(max(gy0 + y, 0), IMG - 1);
            const int gx = min(max(gx0 + x, 0), IMG - 1);
            cur[y * RWP + x] = img[(size_t)gy * IMG + gx];
        }
    }
    __syncthreads();

    const bool topE   = (by == 0);
    const bool botE   = (by == (int)gridDim.y - 1);
    const bool leftE  = (bx == 0);
    const bool rightE = (bx == (int)gridDim.x - 1);

    const int c  = tid % NCOL;                   // float4 column 0..37
    const int s  = tid / NCOL;                   // strip 0..18
    const int xb = c * 4;                        // 0..148
    const bool dcol  = (xb >= HALO) && (xb + 4 <= HALO + TILE);  // interior col block
    const bool lClip = leftE  && (c == 3);       // block containing image col 0
    const bool rClip = rightE && (c == 34);      // block containing image col 1023
    const int y0 = s * RPS;
    // strip intersects the dilate accumulation band [HALO, HALO+TILE)?
    const bool dstrip = (y0 < HALO + TILE) && (y0 + RPS > HALO);

    float4 acc[RPS];
#pragma unroll
    for (int k = 0; k < RPS; k++) acc[k] = make_float4(0.f, 0.f, 0.f, 0.f);

    for (int p = 0; p <= K; ++p) {
        const bool doE = (p < K);
        const int  m   = K - p;                  // erode validity margin
        const int  elo = doE ? (HALO - m) : 0;
        const int  ehi = doE ? (HALO + TILE + m) : 0;
        // strip-level work predicates
        const bool needE = doE && (y0 < ehi) && (y0 + RPS > elo);
        const bool needD = (p > 0) && dcol && dstrip;

        if (needE || needD) {
            // prime 3-row ring (vertical replicate clamp; min-safe, clamped
            // rows never reach clipped dilate consumers)
            float4 av, amn, amx, bv, bmn, bmx;
            rowmm(cur + max(y0 - 1, 0) * RWP, xb, av, amn, amx, needE, needD, lClip, rClip);
            rowmm(cur + y0 * RWP,             xb, bv, bmn, bmx, needE, needD, lClip, rClip);

#pragma unroll
            for (int k = 0; k < RPS; k++) {
                const int y = y0 + k;
                float4 cv, cmn, cmx;
                rowmm(cur + min(y + 1, RW - 1) * RWP, xb, cv, cmn, cmx,
                      needE, needD, lClip, rClip);

                // skel terms at interior rows: += x_p (p<K), -= dilate(x_p) (p>0)
                if (y >= HALO && y < HALO + TILE) {
                    if (needD) {
                        // vertical clipping at image top/bottom rows (registers)
                        float4 A = amx, C = cmx;
                        if (topE && y == HALO)            A = bmx;
                        if (botE && y == HALO + TILE - 1) C = bmx;
                        acc[k].x -= max3f(A.x, bmx.x, C.x);
                        acc[k].y -= max3f(A.y, bmx.y, C.y);
                        acc[k].z -= max3f(A.z, bmx.z, C.z);
                        acc[k].w -= max3f(A.w, bmx.w, C.w);
                    }
                    if (doE && dcol) {
                        acc[k].x += bv.x; acc[k].y += bv.y;
                        acc[k].z += bv.z; acc[k].w += bv.w;
                    }
                }
                // erode -> x_{p+1}
                if (needE && y >= elo && y < ehi) {
                    float4 e;
                    e.x = min3f(amn.x, bmn.x, cmn.x);
                    e.y = min3f(amn.y, bmn.y, cmn.y);
                    e.z = min3f(amn.z, bmn.z, cmn.z);
                    e.w = min3f(amn.w, bmn.w, cmn.w);
                    *(float4*)(nxt + y * RWP + xb) = e;
                }
                av = bv; amn = bmn; amx = bmx;
                bv = cv; bmn = cmn; bmx = cmx;
            }
        }
        __syncthreads();

        if (doE) { float* t = cur; cur = nxt; nxt = t; }
    }

    // ---- outputs ----
    if (dcol) {
        float* so = skel + (size_t)bz * IMG * IMG;
        float* xo = xout + (size_t)bz * IMG * IMG;
#pragma unroll
        for (int k = 0; k < RPS; k++) {
            const int y = y0 + k;
            if (y >= HALO && y < HALO + TILE) {
                const size_t off = (size_t)(by * TILE + (y - HALO)) * IMG
                                 + (size_t)(bx * TILE + (xb - HALO));
                if (writex)
                    *(float4*)(xo + off) = *(const float4*)(cur + y * RWP + xb);
                if (accum) {
                    float4 sv = *(const float4*)(so + off);
                    sv.x += acc[k].x; sv.y += acc[k].y;
                    sv.z += acc[k].z; sv.w += acc[k].w;
                    *(float4*)(so + off) = sv;
                } else {
                    *(float4*)(so + off) = acc[k];
                }
            }
        }
    }
}

extern "C" void kernel_launch(void* const* d_in, const int* in_sizes, int n_in,
                              void* d_out, int out_size)
{
    (void)in_sizes; (void)n_in; (void)out_size;
    const float* x = (const float*)d_in[0];
    float* skel = (float*)d_out;

    float* scratch = nullptr;
    cudaGetSymbolAddress((void**)&scratch, g_scratch);

    cudaFuncSetAttribute(skel_merged_kernel,
                         cudaFuncAttributeMaxDynamicSharedMemorySize, SMEMB);

    dim3 grid(IMG / TILE, IMG / TILE, NIMG);   // 8 x 8 x 16
    // iterations 0..10 (11 terms): init skel, write x_11 to scratch
    skel_merged_kernel<<<grid, NT, SMEMB>>>(x, scratch, skel, 11, 0, 1);
    // iterations 11..20 (10 terms): accumulate skel
    skel_merged_kernel<<<grid, NT, SMEMB>>>(scratch, scratch, skel, 10, 1, 0);
}

// round 15
// speedup vs baseline: 1.2586x; 1.2249x over previous
#include <cuda_runtime.h>
#include <cuda_fp16.h>

//
// Morphological skeleton — merged erode+dilate, one smem pass per iteration.
// R14 = R10 (best: 492us) with the smem data plane in fp16:
//   - erosion/dilation are SELECTIONS (no arithmetic), so after one initial
//     fp32->fp16 quantization every iterate is exact over the quantized field;
//     error is bounded by the single quantization (~2.4e-4 RMS), accumulator
//     stays fp32.
//   - crossbar bytes halve (LDS.64 center, STS.64 erode store), min/max run
//     2 lanes/instr via __hmin2/__hmax2 with register-packed shifted pairs.
//   - scratch x_11 is stored fp16 (no re-quantization between launches).
// Border ring fix-up pass restored verbatim from R10 (R13 proved the halo
// replica property does NOT self-maintain under erosion).
//
//   skel = sum_{j=0..K-1} x_j  -  sum_{j=1..K} dilate3(x_j),  x_{j+1} = erode3(x_j)
//

#define IMG    1024
#define NIMG   16
#define TILE   128
#define HALO   12
#define RW     152                 /* region valid width/height          */
#define RWP    164                 /* row stride in HALVES               */
#define NCOL   38                  /* 4-px blocks per row (4*38 = 152)   */
#define NSTR   19
#define NT     (NCOL*NSTR)         /* 722 threads ~ 22.6 warps           */
#define RPS    8                   /* rows per strip: 19*8 = 152 exactly */
#define BUFH   (RW*RWP)            /* halves per buffer                  */
#define SMEMB  (2*BUFH*2)          /* 99712 bytes                        */

__device__ __half g_scratch[(size_t)NIMG * IMG * IMG];

struct RowH {
    __half2 c0, c1;      // raw x at cols 4c..4c+3
    __half2 mn0, mn1;    // horizontal 3-min pairs
    __half2 mx0, mx1;    // horizontal 3-max pairs
};

// One row-block: LDS.64 center + 2 scalar half LDS; shifted pairs are packed
// in registers (no shuffles). doMn/doMx block-uniform-ish predicates.
__device__ __forceinline__ void rowmm(const __half* __restrict__ row, int xb,
                                      RowH& o, bool doMn, bool doMx)
{
    const uint2 u = *(const uint2*)(row + xb);          // 8B aligned (xb%4==0)
    __half2 c0 = *reinterpret_cast<const __half2*>(&u.x);
    __half2 c1 = *reinterpret_cast<const __half2*>(&u.y);
    const __half l = (xb > 0)      ? row[xb - 1] : __low2half(c0);   // replicate
    const __half r = (xb + 4 < RW) ? row[xb + 4] : __high2half(c1);  // (min-safe)
    const __half2 sl  = __halves2half2(l, __low2half(c0));            // [x-1,x0]
    const __half2 mid = __halves2half2(__high2half(c0), __low2half(c1)); // [x1,x2]
    const __half2 sr  = __halves2half2(__high2half(c1), r);           // [x3,x+4]
    o.c0 = c0; o.c1 = c1;
    if (doMn) {
        o.mn0 = __hmin2(__hmin2(sl, c0), mid);
        o.mn1 = __hmin2(__hmin2(mid, c1), sr);
    }
    if (doMx) {
        o.mx0 = __hmax2(__hmax2(sl, c0), mid);
        o.mx1 = __hmax2(__hmax2(mid, c1), sr);
    }
}

__global__ void __launch_bounds__(NT, 1)
skel_h_kernel(const float* __restrict__ xin,       // fp32 input (launch 1)
              const __half* __restrict__ hin,      // fp16 input (launch 2)
              __half* __restrict__ xout,           // fp16 x_K out
              float* __restrict__ skel,
              int K, int accum, int writex, int halfin)
{
    extern __shared__ __half smem[];
    __half* cur = smem;            // x_p
    __half* nxt = smem + BUFH;     // receives x_{p+1}

    const int tid = threadIdx.x;
    const int bx = blockIdx.x, by = blockIdx.y, bz = blockIdx.z;
    const int gx0 = bx * TILE - HALO;
    const int gy0 = by * TILE - HALO;

    // ---- load region with replicate clamp (quantize fp32 -> fp16 once) ----
    if (halfin) {
        const __half* img = hin + (size_t)bz * IMG * IMG;
        for (int i = tid; i < RW * RW; i += NT) {
            int y = i / RW;
            int x = i - y * RW;
            int gy = min(max(gy0 + y, 0), IMG - 1);
            int gx = min(max(gx0 + x, 0), IMG - 1);
            cur[y * RWP + x] = img[(size_t)gy * IMG + gx];
        }
    } else {
        const float* img = xin + (size_t)bz * IMG * IMG;
        for (int i = tid; i < RW * RW; i += NT) {
            int y = i / RW;
            int x = i - y * RW;
            int gy = min(max(gy0 + y, 0), IMG - 1);
            int gx = min(max(gx0 + x, 0), IMG - 1);
            cur[y * RWP + x] = __float2half_rn(img[(size_t)gy * IMG + gx]);
        }
    }
    __syncthreads();

    const bool topE   = (by == 0);
    const bool botE   = (by == (int)gridDim.y - 1);
    const bool leftE  = (bx == 0);
    const bool rightE = (bx == (int)gridDim.x - 1);
    const bool anyE   = topE || botE || leftE || rightE;

    const int c  = tid % NCOL;                   // block column 0..37
    const int s  = tid / NCOL;                   // strip 0..18
    const int xb = c * 4;                        // 0..148 (half index)
    const bool dcol = (xb >= HALO) && (xb + 4 <= HALO + TILE);  // interior cols
    const int y0 = s * RPS;

    float4 acc[RPS];
#pragma unroll
    for (int k = 0; k < RPS; k++) acc[k] = make_float4(0.f, 0.f, 0.f, 0.f);

    for (int p = 0; p <= K; ++p) {
        const bool doE = (p < K);
        const bool doD = (p > 0);
        const bool doMx = doD && dcol;           // hmax consumed only here
        const int  m   = K - p;                  // erode validity margin
        const int  elo = doE ? (HALO - m) : HALO;
        const int  ehi = doE ? (HALO + TILE + m) : (HALO + TILE);

        if (doE || dcol) {
            // prime 3-row ring (vertical replicate clamp at region edges)
            RowH A, B, C;
            rowmm(cur + max(y0 - 1, 0) * RWP, xb, A, doE, doMx);
            rowmm(cur + y0 * RWP,             xb, B, doE, doMx);

#pragma unroll
            for (int k = 0; k < RPS; k++) {
                const int y = y0 + k;
                rowmm(cur + min(y + 1, RW - 1) * RWP, xb, C, doE, doMx);

                // skel terms at interior rows: += x_p (p<K), -= dilate(x_p) (p>0)
                if (dcol && y >= HALO && y < HALO + TILE) {
                    if (doMx) {
                        const __half2 d0 = __hmax2(__hmax2(A.mx0, B.mx0), C.mx0);
                        const __half2 d1 = __hmax2(__hmax2(A.mx1, B.mx1), C.mx1);
                        const float2 f0 = __half22float2(d0);
                        const float2 f1 = __half22float2(d1);
                        acc[k].x -= f0.x; acc[k].y -= f0.y;
                        acc[k].z -= f1.x; acc[k].w -= f1.y;
                    }
                    if (doE) {
                        const float2 b0 = __half22float2(B.c0);
                        const float2 b1 = __half22float2(B.c1);
                        acc[k].x += b0.x; acc[k].y += b0.y;
                        acc[k].z += b1.x; acc[k].w += b1.y;
                    }
                }
                // erode -> x_{p+1}
                if (doE && y >= elo && y < ehi) {
                    const __half2 e0 = __hmin2(__hmin2(A.mn0, B.mn0), C.mn0);
                    const __half2 e1 = __hmin2(__hmin2(A.mn1, B.mn1), C.mn1);
                    uint2 w;
                    w.x = *reinterpret_cast<const unsigned*>(&e0);
                    w.y = *reinterpret_cast<const unsigned*>(&e1);
                    *(uint2*)(nxt + y * RWP + xb) = w;
                }
                A = B; B = C;
            }
        }
        __syncthreads();

        // image-border ring fix-up on freshly eroded buffer (edge blocks only):
        // the inner halo ring must hold exact boundary replicas of e so that
        // the unclipped dilate equals the clipped dilate (R13 proved this is
        // NOT self-maintaining).
        if (doE && anyE) {
            if (tid < TILE + 2) {
                int o = HALO - 1 + tid;                    // 11..140
                int sx = o;
                if (leftE  && sx < HALO)             sx = HALO;
                if (rightE && sx > HALO + TILE - 1)  sx = HALO + TILE - 1;
                int sy = o;
                if (topE && sy < HALO)               sy = HALO;
                if (botE && sy > HALO + TILE - 1)    sy = HALO + TILE - 1;
                if (topE)   nxt[(HALO - 1) * RWP + o]      = nxt[HALO * RWP + sx];
                if (botE)   nxt[(HALO + TILE) * RWP + o]   = nxt[(HALO + TILE - 1) * RWP + sx];
                if (leftE)  nxt[o * RWP + (HALO - 1)]      = nxt[sy * RWP + HALO];
                if (rightE) nxt[o * RWP + (HALO + TILE)]   = nxt[sy * RWP + (HALO + TILE - 1)];
            }
            __syncthreads();
        }

        if (doE) { __half* t = cur; cur = nxt; nxt = t; }
    }

    // ---- outputs ----
    if (dcol) {
        float* so = skel + (size_t)bz * IMG * IMG;
        __half* xo = xout + (size_t)bz * IMG * IMG;
#pragma unroll
        for (int k = 0; k < RPS; k++) {
            const int y = y0 + k;
            if (y >= HALO && y < HALO + TILE) {
                const size_t off = (size_t)(by * TILE + (y - HALO)) * IMG
                                 + (size_t)(bx * TILE + (xb - HALO));
                if (writex)
                    *(uint2*)(xo + off) = *(const uint2*)(cur + y * RWP + xb);
                if (accum) {
                    float4 sv = *(const float4*)(so + off);
                    sv.x += acc[k].x; sv.y += acc[k].y;
                    sv.z += acc[k].z; sv.w += acc[k].w;
                    *(float4*)(so + off) = sv;
                } else {
                    *(float4*)(so + off) = acc[k];
                }
            }
        }
    }
}

extern "C" void kernel_launch(void* const* d_in, const int* in_sizes, int n_in,
                              void* d_out, int out_size)
{
    (void)in_sizes; (void)n_in; (void)out_size;
    const float* x = (const float*)d_in[0];
    float* skel = (float*)d_out;

    __half* scratch = nullptr;
    cudaGetSymbolAddress((void**)&scratch, g_scratch);

    cudaFuncSetAttribute(skel_h_kernel,
                         cudaFuncAttributeMaxDynamicSharedMemorySize, SMEMB);

    dim3 grid(IMG / TILE, IMG / TILE, NIMG);   // 8 x 8 x 16
    // iterations 0..10 (11 terms): init skel, write x_11 (fp16) to scratch
    skel_h_kernel<<<grid, NT, SMEMB>>>(x, nullptr, scratch, skel, 11, 0, 1, 0);
    // iterations 11..20 (10 terms): accumulate skel
    skel_h_kernel<<<grid, NT, SMEMB>>>(nullptr, scratch, scratch, skel, 10, 1, 0, 1);
}